// round 11
// baseline (speedup 1.0000x reference)
#include <cuda_runtime.h>

#define D 128
#define KN 32
#define MAXB 20000
#define GROWS 160          // rows per gemm block
#define GPAD 164           // padded row-dim for transposed agg tile

__device__ float g_u[D];
__device__ float g_v[D];
__device__ float g_M[D * D];
__device__ float g_agg[MAXB * D];

// packed f32x2 FMA (Blackwell): acc = a*b + acc lanewise (exact fp32, 2 lanes)
#define FMA2(acc, a, b) \
    asm("fma.rn.f32x2 %0, %1, %2, %0;" : "+l"(acc) : "l"(a), "l"(b))

// ---------------------------------------------------------------------------
// Kernel P1: u/v precompute. 2 blocks x 128 threads (measured form).
// ---------------------------------------------------------------------------
__global__ __launch_bounds__(128) void prep_uv(
    const float* __restrict__ kernel0,
    const float* __restrict__ kernel1,
    const float* __restrict__ aw) {
    int t    = threadIdx.x;
    int lane = t & 31;
    int w    = t >> 5;

    const float* mat = (blockIdx.x == 0) ? kernel1 : kernel0;
    const float* a   = aw + blockIdx.x * D;
    float*       out = (blockIdx.x == 0) ? g_u : g_v;

    float4 av = ((const float4*)a)[lane];
    const float4* m4 = (const float4*)mat;
#pragma unroll
    for (int j = 0; j < 32; ++j) {
        int r = w * 32 + j;
        float4 x = m4[r * 32 + lane];
        float s = x.x * av.x + x.y * av.y + x.z * av.z + x.w * av.w;
#pragma unroll
        for (int o = 16; o > 0; o >>= 1) s += __shfl_xor_sync(0xffffffffu, s, o);
        if (lane == 0) out[r] = s;
    }
}

// ---------------------------------------------------------------------------
// Kernel P2: M precompute — direct coalesced LDG (nw L2-resident), no staging.
// ---------------------------------------------------------------------------
__global__ __launch_bounds__(128) void prep_M(
    const float* __restrict__ kernel1,
    const float* __restrict__ nw) {
    __shared__ float krow[D];

    int b = blockIdx.x;
    int t = threadIdx.x;

    krow[t] = kernel1[b * D + t];
    __syncthreads();

    float acc = 0.f;
#pragma unroll 8
    for (int j = 0; j < D; ++j)
        acc += krow[j] * __ldg(&nw[j * D + t]);
    g_M[b * D + t] = acc;
}

// ---------------------------------------------------------------------------
// Kernel A: per-target attention — exact R8-measured form (52.8us).
// ---------------------------------------------------------------------------
__global__ __launch_bounds__(128) void attn_kernel(
    const float* __restrict__ features,
    const int* __restrict__ node,
    const int* __restrict__ neigh,
    int B) {
    __shared__ float scores[KN];
    __shared__ float wts[KN];
    __shared__ float part[4 * D];

    int b = blockIdx.x;
    if (b >= B) return;
    int tid  = threadIdx.x;
    int lane = tid & 31;
    int w    = tid >> 5;

    const float4* f4 = (const float4*)features;

    float4 x[8];
#pragma unroll
    for (int it = 0; it < 8; ++it) {
        int k  = it * 4 + w;
        int nb = __ldg(&neigh[b * KN + k]);
        x[it]  = f4[(size_t)nb * 32 + lane];
    }

    int nd = __ldg(&node[b]);
    float4 fv = f4[(size_t)nd * 32 + lane];
    float4 vv = ((const float4*)g_v)[lane];
    float sn = fv.x * vv.x + fv.y * vv.y + fv.z * vv.z + fv.w * vv.w;
#pragma unroll
    for (int o = 16; o > 0; o >>= 1) sn += __shfl_xor_sync(0xffffffffu, sn, o);

    float4 uu = ((const float4*)g_u)[lane];
#pragma unroll
    for (int it = 0; it < 8; ++it) {
        float s = x[it].x * uu.x + x[it].y * uu.y + x[it].z * uu.z + x[it].w * uu.w;
#pragma unroll
        for (int o = 16; o > 0; o >>= 1) s += __shfl_xor_sync(0xffffffffu, s, o);
        if (lane == 0) {
            float t = s + sn;
            scores[it * 4 + w] = (t > 0.f) ? t : 0.2f * t;
        }
    }
    __syncthreads();

    if (w == 0) {
        float sc = scores[lane];
        float m = sc;
#pragma unroll
        for (int o = 16; o > 0; o >>= 1) m = fmaxf(m, __shfl_xor_sync(0xffffffffu, m, o));
        float e = __expf(sc - m);
        float den = e;
#pragma unroll
        for (int o = 16; o > 0; o >>= 1) den += __shfl_xor_sync(0xffffffffu, den, o);
        wts[lane] = e / den;
    }
    __syncthreads();

    float4 p = make_float4(0.f, 0.f, 0.f, 0.f);
#pragma unroll
    for (int it = 0; it < 8; ++it) {
        float wk = wts[it * 4 + w];
        p.x += wk * x[it].x;
        p.y += wk * x[it].y;
        p.z += wk * x[it].z;
        p.w += wk * x[it].w;
    }
    ((float4*)part)[w * 32 + lane] = p;
    __syncthreads();

    float acc = part[tid] + part[D + tid] + part[2 * D + tid] + part[3 * D + tid];
    g_agg[b * D + tid] = acc;
}

// ---------------------------------------------------------------------------
// Kernel G v4: out = agg @ M. 640 threads (40 ty x 16 tx), block = 160 rows,
// 4x8 register tile per thread. Same smem (146 KB) but 20 warps/SM
// (5 warps/SMSP) to hide LDS latency. FMA2 inner loop.
// ---------------------------------------------------------------------------
__global__ __launch_bounds__(640) void out_gemm(float* __restrict__ out, int B) {
    extern __shared__ float sm[];
    float* Ms  = sm;             // D*D floats (64 KB)
    float* aTs = sm + D * D;     // D * GPAD floats (82 KB), [d*GPAD + row]

    int tid = threadIdx.x;
    int r0  = blockIdx.x * GROWS;

    // stage M (640 threads)
    float4*       Ms4 = (float4*)Ms;
    const float4* gM4 = (const float4*)g_M;
    for (int i = tid; i < (D * D) / 4; i += 640) Ms4[i] = gM4[i];

    // stage agg tile transposed: 4 threads per row, each covers 32 d
    {
        int row = tid >> 2;            // 0..159
        int q   = tid & 3;             // d-quarter
        bool rv = (r0 + row) < B;
        const float4* ga = (const float4*)g_agg + (size_t)(r0 + row) * 32 + q * 8;
#pragma unroll
        for (int i = 0; i < 8; ++i) {
            float4 f = rv ? ga[i] : make_float4(0.f, 0.f, 0.f, 0.f);
            int d = q * 32 + i * 4;
            aTs[(d + 0) * GPAD + row] = f.x;
            aTs[(d + 1) * GPAD + row] = f.y;
            aTs[(d + 2) * GPAD + row] = f.z;
            aTs[(d + 3) * GPAD + row] = f.w;
        }
    }
    __syncthreads();

    int ty = tid >> 4;   // 0..39 -> rows ty*4..ty*4+3
    int tx = tid & 15;   // 0..15 -> cols tx*8..tx*8+7

    unsigned long long acc[4][4];
#pragma unroll
    for (int i = 0; i < 4; ++i)
#pragma unroll
        for (int j = 0; j < 4; ++j) acc[i][j] = 0ull;

#pragma unroll 8
    for (int d = 0; d < D; ++d) {
        float4 a0 = *(const float4*)(aTs + d * GPAD + ty * 4);   // 4 rows
        ulonglong2 m01 = *(const ulonglong2*)(Ms + d * D + tx * 8);
        ulonglong2 m23 = *(const ulonglong2*)(Ms + d * D + tx * 8 + 4);
        float ar[4] = {a0.x, a0.y, a0.z, a0.w};
#pragma unroll
        for (int i = 0; i < 4; ++i) {
            unsigned long long mm;
            asm("mov.b64 %0, {%1, %1};" : "=l"(mm) : "f"(ar[i]));
            FMA2(acc[i][0], m01.x, mm);
            FMA2(acc[i][1], m01.y, mm);
            FMA2(acc[i][2], m23.x, mm);
            FMA2(acc[i][3], m23.y, mm);
        }
    }

    // epilogue: unpack + store (4 rows x 8 cols)
#pragma unroll
    for (int i = 0; i < 4; ++i) {
        int row = r0 + ty * 4 + i;
        if (row < B) {
            float r_[8];
            asm("mov.b64 {%0, %1}, %2;" : "=f"(r_[0]), "=f"(r_[1]) : "l"(acc[i][0]));
            asm("mov.b64 {%0, %1}, %2;" : "=f"(r_[2]), "=f"(r_[3]) : "l"(acc[i][1]));
            asm("mov.b64 {%0, %1}, %2;" : "=f"(r_[4]), "=f"(r_[5]) : "l"(acc[i][2]));
            asm("mov.b64 {%0, %1}, %2;" : "=f"(r_[6]), "=f"(r_[7]) : "l"(acc[i][3]));
            float4* o4 = (float4*)(out + (size_t)row * D + tx * 8);
            o4[0] = make_float4(r_[0], r_[1], r_[2], r_[3]);
            o4[1] = make_float4(r_[4], r_[5], r_[6], r_[7]);
        }
    }
}

// ---------------------------------------------------------------------------
extern "C" void kernel_launch(void* const* d_in, const int* in_sizes, int n_in,
                              void* d_out, int out_size) {
    const float* features = (const float*)d_in[0];
    const int*   node     = (const int*)d_in[1];
    const int*   neigh    = (const int*)d_in[2];
    const float* kern0    = (const float*)d_in[3];
    const float* kern1    = (const float*)d_in[4];
    const float* aw       = (const float*)d_in[5];
    const float* nw       = (const float*)d_in[6];
    float*       out      = (float*)d_out;

    int B = in_sizes[1];
    if (B > MAXB) B = MAXB;

    prep_uv<<<2, D>>>(kern0, kern1, aw);                       // 1
    prep_M<<<D, D>>>(kern1, nw);                               // 2
    attn_kernel<<<B, D>>>(features, node, neigh, B);           // 3

    const int gemm_smem = (D * D + D * GPAD) * sizeof(float);  // ~146 KB
    cudaFuncSetAttribute(out_gemm, cudaFuncAttributeMaxDynamicSharedMemorySize, gemm_smem);
    int gblocks = (B + GROWS - 1) / GROWS;                     // 125 for B=20000
    out_gemm<<<gblocks, 640, gemm_smem>>>(out, B);             // 4 (profiled)
}

// round 12
// speedup vs baseline: 1.0003x; 1.0003x over previous
#include <cuda_runtime.h>

#define D 128
#define KN 32
#define MAXB 20000
#define GROWS 96           // rows per gemm block
#define GPAD 100           // padded row-dim for transposed agg tile

__device__ float g_u[D];
__device__ float g_v[D];
__device__ float g_M[D * D];
__device__ float g_agg[MAXB * D];

// packed f32x2 FMA (Blackwell): acc = a*b + acc lanewise (exact fp32, 2 lanes)
#define FMA2(acc, a, b) \
    asm("fma.rn.f32x2 %0, %1, %2, %0;" : "+l"(acc) : "l"(a), "l"(b))

// ---------------------------------------------------------------------------
// Kernel P1: u/v precompute. 2 blocks x 128 threads (measured form).
// ---------------------------------------------------------------------------
__global__ __launch_bounds__(128) void prep_uv(
    const float* __restrict__ kernel0,
    const float* __restrict__ kernel1,
    const float* __restrict__ aw) {
    int t    = threadIdx.x;
    int lane = t & 31;
    int w    = t >> 5;

    const float* mat = (blockIdx.x == 0) ? kernel1 : kernel0;
    const float* a   = aw + blockIdx.x * D;
    float*       out = (blockIdx.x == 0) ? g_u : g_v;

    float4 av = ((const float4*)a)[lane];
    const float4* m4 = (const float4*)mat;
#pragma unroll
    for (int j = 0; j < 32; ++j) {
        int r = w * 32 + j;
        float4 x = m4[r * 32 + lane];
        float s = x.x * av.x + x.y * av.y + x.z * av.z + x.w * av.w;
#pragma unroll
        for (int o = 16; o > 0; o >>= 1) s += __shfl_xor_sync(0xffffffffu, s, o);
        if (lane == 0) out[r] = s;
    }
}

// ---------------------------------------------------------------------------
// Kernel P2: M precompute — R8/R10-measured smem-staging form (~8.5us).
// ---------------------------------------------------------------------------
__global__ __launch_bounds__(128) void prep_M(
    const float* __restrict__ kernel1,
    const float* __restrict__ nw) {
    extern __shared__ float psm[];
    float* nws  = psm;          // D*D floats (64KB)
    float* krow = psm + D * D;  // D floats

    int b = blockIdx.x;
    int t = threadIdx.x;

    krow[t] = kernel1[b * D + t];
    const float4* nw4  = (const float4*)nw;
    float4*       nws4 = (float4*)nws;
#pragma unroll
    for (int it = 0; it < 32; ++it)
        nws4[it * 128 + t] = nw4[it * 128 + t];
    __syncthreads();

    float acc = 0.f;
#pragma unroll 16
    for (int j = 0; j < D; ++j)
        acc += krow[j] * nws[j * D + t];
    g_M[b * D + t] = acc;
}

// ---------------------------------------------------------------------------
// Kernel A: per-target attention — exact R8-measured form (52.8us).
// ---------------------------------------------------------------------------
__global__ __launch_bounds__(128) void attn_kernel(
    const float* __restrict__ features,
    const int* __restrict__ node,
    const int* __restrict__ neigh,
    int B) {
    __shared__ float scores[KN];
    __shared__ float wts[KN];
    __shared__ float part[4 * D];

    int b = blockIdx.x;
    if (b >= B) return;
    int tid  = threadIdx.x;
    int lane = tid & 31;
    int w    = tid >> 5;

    const float4* f4 = (const float4*)features;

    float4 x[8];
#pragma unroll
    for (int it = 0; it < 8; ++it) {
        int k  = it * 4 + w;
        int nb = __ldg(&neigh[b * KN + k]);
        x[it]  = f4[(size_t)nb * 32 + lane];
    }

    int nd = __ldg(&node[b]);
    float4 fv = f4[(size_t)nd * 32 + lane];
    float4 vv = ((const float4*)g_v)[lane];
    float sn = fv.x * vv.x + fv.y * vv.y + fv.z * vv.z + fv.w * vv.w;
#pragma unroll
    for (int o = 16; o > 0; o >>= 1) sn += __shfl_xor_sync(0xffffffffu, sn, o);

    float4 uu = ((const float4*)g_u)[lane];
#pragma unroll
    for (int it = 0; it < 8; ++it) {
        float s = x[it].x * uu.x + x[it].y * uu.y + x[it].z * uu.z + x[it].w * uu.w;
#pragma unroll
        for (int o = 16; o > 0; o >>= 1) s += __shfl_xor_sync(0xffffffffu, s, o);
        if (lane == 0) {
            float t = s + sn;
            scores[it * 4 + w] = (t > 0.f) ? t : 0.2f * t;
        }
    }
    __syncthreads();

    if (w == 0) {
        float sc = scores[lane];
        float m = sc;
#pragma unroll
        for (int o = 16; o > 0; o >>= 1) m = fmaxf(m, __shfl_xor_sync(0xffffffffu, m, o));
        float e = __expf(sc - m);
        float den = e;
#pragma unroll
        for (int o = 16; o > 0; o >>= 1) den += __shfl_xor_sync(0xffffffffu, den, o);
        wts[lane] = e / den;
    }
    __syncthreads();

    float4 p = make_float4(0.f, 0.f, 0.f, 0.f);
#pragma unroll
    for (int it = 0; it < 8; ++it) {
        float wk = wts[it * 4 + w];
        p.x += wk * x[it].x;
        p.y += wk * x[it].y;
        p.z += wk * x[it].z;
        p.w += wk * x[it].w;
    }
    ((float4*)part)[w * 32 + lane] = p;
    __syncthreads();

    float acc = part[tid] + part[D + tid] + part[2 * D + tid] + part[3 * D + tid];
    g_agg[b * D + tid] = acc;
}

// ---------------------------------------------------------------------------
// Kernel G v5: out = agg @ M. 192 threads (12 ty x 16 tx), block = 96 rows,
// 8x8 register tile per thread (v3-measured tile shape), FMA2.
// M read via __ldg (L1-resident 64KB) instead of smem -> smem is only the
// 48KB transposed agg tile -> 3 blocks/SM = 18 warps/SM (vs v3's 10).
// ---------------------------------------------------------------------------
__global__ __launch_bounds__(192) void out_gemm(const float* __restrict__ Mg,
                                                float* __restrict__ out, int B) {
    extern __shared__ float sm[];
    float* aTs = sm;             // D * GPAD floats (~50 KB), [d*GPAD + row]

    int tid = threadIdx.x;
    int r0  = blockIdx.x * GROWS;

    // stage agg tile transposed: 2 threads per row, each covers 64 d
    {
        int row  = tid >> 1;           // 0..95
        int half = tid & 1;            // d-half
        bool rv  = (r0 + row) < B;
        const float4* ga = (const float4*)g_agg + (size_t)(r0 + row) * 32 + half * 16;
#pragma unroll
        for (int i = 0; i < 16; ++i) {
            float4 f = rv ? ga[i] : make_float4(0.f, 0.f, 0.f, 0.f);
            int d = half * 64 + i * 4;
            aTs[(d + 0) * GPAD + row] = f.x;
            aTs[(d + 1) * GPAD + row] = f.y;
            aTs[(d + 2) * GPAD + row] = f.z;
            aTs[(d + 3) * GPAD + row] = f.w;
        }
    }
    __syncthreads();

    int ty = tid >> 4;   // 0..11 -> rows ty*8..ty*8+7
    int tx = tid & 15;   // 0..15 -> cols tx*8..tx*8+7

    unsigned long long acc[8][4];
#pragma unroll
    for (int i = 0; i < 8; ++i)
#pragma unroll
        for (int j = 0; j < 4; ++j) acc[i][j] = 0ull;

    const ulonglong2* M2 = (const ulonglong2*)(Mg);   // 16B granules

#pragma unroll 4
    for (int d = 0; d < D; ++d) {
        float4 a0 = *(const float4*)(aTs + d * GPAD + ty * 8);
        float4 a1 = *(const float4*)(aTs + d * GPAD + ty * 8 + 4);
        ulonglong2 m01 = __ldg(&M2[(d * D + tx * 8) >> 2]);
        ulonglong2 m23 = __ldg(&M2[(d * D + tx * 8 + 4) >> 2]);
        float ar[8] = {a0.x, a0.y, a0.z, a0.w, a1.x, a1.y, a1.z, a1.w};
#pragma unroll
        for (int i = 0; i < 8; ++i) {
            unsigned long long mm;
            asm("mov.b64 %0, {%1, %1};" : "=l"(mm) : "f"(ar[i]));
            FMA2(acc[i][0], m01.x, mm);
            FMA2(acc[i][1], m01.y, mm);
            FMA2(acc[i][2], m23.x, mm);
            FMA2(acc[i][3], m23.y, mm);
        }
    }

    // epilogue: unpack + store
#pragma unroll
    for (int i = 0; i < 8; ++i) {
        int row = r0 + ty * 8 + i;
        if (row < B) {
            float r_[8];
            asm("mov.b64 {%0, %1}, %2;" : "=f"(r_[0]), "=f"(r_[1]) : "l"(acc[i][0]));
            asm("mov.b64 {%0, %1}, %2;" : "=f"(r_[2]), "=f"(r_[3]) : "l"(acc[i][1]));
            asm("mov.b64 {%0, %1}, %2;" : "=f"(r_[4]), "=f"(r_[5]) : "l"(acc[i][2]));
            asm("mov.b64 {%0, %1}, %2;" : "=f"(r_[6]), "=f"(r_[7]) : "l"(acc[i][3]));
            float4* o4 = (float4*)(out + (size_t)row * D + tx * 8);
            o4[0] = make_float4(r_[0], r_[1], r_[2], r_[3]);
            o4[1] = make_float4(r_[4], r_[5], r_[6], r_[7]);
        }
    }
}

// ---------------------------------------------------------------------------
extern "C" void kernel_launch(void* const* d_in, const int* in_sizes, int n_in,
                              void* d_out, int out_size) {
    const float* features = (const float*)d_in[0];
    const int*   node     = (const int*)d_in[1];
    const int*   neigh    = (const int*)d_in[2];
    const float* kern0    = (const float*)d_in[3];
    const float* kern1    = (const float*)d_in[4];
    const float* aw       = (const float*)d_in[5];
    const float* nw       = (const float*)d_in[6];
    float*       out      = (float*)d_out;

    int B = in_sizes[1];
    if (B > MAXB) B = MAXB;

    prep_uv<<<2, D>>>(kern0, kern1, aw);                       // 1

    const int prepM_smem = (D * D + D) * sizeof(float);        // ~66 KB
    cudaFuncSetAttribute(prep_M, cudaFuncAttributeMaxDynamicSharedMemorySize, prepM_smem);
    prep_M<<<D, D, prepM_smem>>>(kern1, nw);                   // 2

    attn_kernel<<<B, D>>>(features, node, neigh, B);           // 3

    float* Mg = nullptr;
    cudaGetSymbolAddress((void**)&Mg, g_M);
    const int gemm_smem = (D * GPAD) * sizeof(float);          // ~50 KB
    cudaFuncSetAttribute(out_gemm, cudaFuncAttributeMaxDynamicSharedMemorySize, gemm_smem);
    int gblocks = (B + GROWS - 1) / GROWS;                     // 209 for B=20000
    out_gemm<<<gblocks, 192, gemm_smem>>>(Mg, out, B);         // 4 (profiled)
}